// round 12
// baseline (speedup 1.0000x reference)
#include <cuda_runtime.h>
#include <cstdint>

// MinArchitecture scan, 2 rows/thread, f16x2-packed smem-LUT gate (LDS.32),
// cp.async pipeline. u-space recurrence per row:
//   u' = G(u)*u + (xs_t - xs_{t+1}),  xs = d0*x ;  out = (xs_511 + G(u)*u)/d0
// LUT entry i (4B): lo f16 = G(u_i), hi f16 = central slope; linear interp.

#define SEQ     512
#define BLOCK   64
#define IL      2
#define TPITCH  68           // floats/thread: 2 rows * 32 + 4 pad; 68*4B = 272B (16B-aligned, conflict-free)
#define NCHUNK  (SEQ / 16)   // 32
#define LUTN    2048
#define LSCALE  64.0f        // entries per unit of u; u range [-16, 16)
#define LOFF    1024.0f
#define MAGIC   8388608.0f   // 2^23

__device__ __forceinline__ unsigned hfma2u(unsigned a, unsigned b, unsigned c) {
    unsigned r;
    asm("fma.rn.f16x2 %0, %1, %2, %3;" : "=r"(r) : "r"(a), "r"(b), "r"(c));
    return r;
}
__device__ __forceinline__ unsigned f2h2(float lo, float hi) {
    unsigned r;
    asm("cvt.rn.f16x2.f32 %0, %2, %1;" : "=r"(r) : "f"(lo), "f"(hi));
    return r;
}
// f16 s in [0,1] (low half) -> f32 bit trick (2 alu ops; denormal f16 -> ~0, harmless)
#define H2F_LO(u) __uint_as_float((((u) << 13) & 0x0FFFE000u) | 0x38000000u)

__global__ void __launch_bounds__(BLOCK) rnn_scan_kernel(
    const float* __restrict__ X,
    const float* __restrict__ W1,
    const float* __restrict__ W2,
    const float* __restrict__ bias,
    const float* __restrict__ Wz,
    const float* __restrict__ Ws,
    float* __restrict__ out)
{
    __shared__ float    sbuf[BLOCK * TPITCH];   // 17408 B (also LUT-build scratch, 4352 >= 2048)
    __shared__ unsigned lut[LUTN];              // 8 KB, f16x2 (g, slope)

    const int lt  = threadIdx.x;
    const int tid = blockIdx.x * BLOCK + lt;
    const size_t r0 = (size_t)tid * IL;

    // ----- uniform scalar constants -----
    const float a1 = 1.0f / (1.0f + expf(W1[1] - W1[0]));
    const float a2 = 1.0f / (1.0f + expf(W2[1] - W2[0]));
    float d0 = a1 - a2;
    if (fabsf(d0) < 1e-20f) d0 = 1e-20f;        // u-space exactly linear in d0
    const float rec = 1.0f / d0;
    const float wz = Wz[0];
    const float ws = Ws[0];
    const float b  = bias[0];
    const float c0 = 0.5f * (b + wz);
    const float c1 = 0.5f * ws;
    const float c2 = -wz;

    // ----- build LUT: G(u_i), u_i = (i - 1024)/64, accurate tanhf -----
    for (int i = lt; i < LUTN; i += BLOCK) {
        float u = ((float)i - LOFF) * (1.0f / LSCALE);
        float t = tanhf(u);
        float y = c0 + c1 * t + c2 * t * t;
        sbuf[i] = 0.5f + 0.5f * tanhf(y);
    }
    __syncthreads();
    for (int i = lt; i < LUTN; i += BLOCK) {
        float gm = sbuf[i > 0 ? i - 1 : 0];
        float gc = sbuf[i];
        float gp = sbuf[i < LUTN - 1 ? i + 1 : LUTN - 1];
        lut[i] = f2h2(gc, 0.5f * (gp - gm));    // lo = g, hi = slope
    }
    __syncthreads();

    // ----- cp.async pipeline, 2 rows per thread -----
    // layout per thread (base 16B-aligned): row0 [0..31], row1 [32..63], pad 4
    // within a row: [0..15] = half A, [16..31] = half B
    float* my = sbuf + lt * TPITCH;

    uint32_t sb;
    {
        uint64_t tmp;
        asm("cvta.to.shared.u64 %0, %1;" : "=l"(tmp) : "l"(my));
        sb = (uint32_t)tmp;
    }

    const float* row0 = X + r0 * SEQ;
    const float* row1 = X + (r0 + 1) * SEQ;

#define ISSUE(half, c) do {                                                    \
        _Pragma("unroll")                                                      \
        for (int j = 0; j < 4; ++j) {                                          \
            asm volatile("cp.async.cg.shared.global [%0], [%1], 16;"           \
                :: "r"(sb + (unsigned)(((half) * 16 + j * 4) * 4)),            \
                   "l"(row0 + (c) * 16 + j * 4) : "memory");                   \
            asm volatile("cp.async.cg.shared.global [%0], [%1], 16;"           \
                :: "r"(sb + (unsigned)((32 + (half) * 16 + j * 4) * 4)),       \
                   "l"(row1 + (c) * 16 + j * 4) : "memory");                   \
        }                                                                      \
        asm volatile("cp.async.commit_group;" ::: "memory");                   \
    } while (0)
#define WAIT1() asm volatile("cp.async.wait_group 1;" ::: "memory")
#define WAIT0() asm volatile("cp.async.wait_group 0;" ::: "memory")

    float uv0 = 0.0f, uv1 = 0.0f;   // u state per row
    float xsp0, xsp1;               // d0 * x_t (previous), per row

    // one step of one row; chain: FFMA -> idx -> LDS.32 -> HFMA2 -> h2f -> FFMA
#define STEP0(XF) do {                                             \
        float xscur = d0 * (XF);                                   \
        float yv    = fmaf(uv0, LSCALE, MAGIC + LOFF);             \
        unsigned e  = lut[__float_as_uint(yv) & (LUTN - 1)];       \
        float rv    = yv - MAGIC;                                  \
        float frac  = fmaf(uv0, LSCALE, LOFF - rv);                \
        unsigned s2 = hfma2u(e >> 16, f2h2(frac, frac), e);        \
        float s     = H2F_LO(s2);                                  \
        uv0 = fmaf(s, uv0, xsp0 - xscur);                          \
        xsp0 = xscur;                                              \
    } while (0)
#define STEP1(XF) do {                                             \
        float xscur = d0 * (XF);                                   \
        float yv    = fmaf(uv1, LSCALE, MAGIC + LOFF);             \
        unsigned e  = lut[__float_as_uint(yv) & (LUTN - 1)];       \
        float rv    = yv - MAGIC;                                  \
        float frac  = fmaf(uv1, LSCALE, LOFF - rv);                \
        unsigned s2 = hfma2u(e >> 16, f2h2(frac, frac), e);        \
        float s     = H2F_LO(s2);                                  \
        uv1 = fmaf(s, uv1, xsp1 - xscur);                          \
        xsp1 = xscur;                                              \
    } while (0)

    // 16 interleaved step-pairs from smem half (E0 = first element to process)
#define PROC(half, E0) do {                                                    \
        _Pragma("unroll")                                                      \
        for (int q = 0; q < 4; ++q) {                                          \
            float4 v0 = *reinterpret_cast<const float4*>(my + (half) * 16 + q * 4);      \
            float4 v1 = *reinterpret_cast<const float4*>(my + 32 + (half) * 16 + q * 4); \
            if (q > 0 || (E0) <= 0) { STEP0(v0.x); STEP1(v1.x); }              \
            if (q > 0 || (E0) <= 1) { STEP0(v0.y); STEP1(v1.y); }              \
            if (q > 0 || (E0) <= 2) { STEP0(v0.z); STEP1(v1.z); }              \
            STEP0(v0.w); STEP1(v1.w);                                          \
        }                                                                      \
    } while (0)

    ISSUE(0, 0);
    ISSUE(1, 1);

    WAIT1();                        // chunk 0 resident
    xsp0 = d0 * my[0];              // xs_0 row0; uv = 0 seeds u_1 on first STEP
    xsp1 = d0 * my[32];             // xs_0 row1
    PROC(0, 1);                     // consume x_1 .. x_15

    #pragma unroll 1
    for (int c = 2; c < NCHUNK; c += 2) {
        ISSUE(0, c);                // prefetch chunk c -> A
        WAIT1();                    // chunk c-1 (B) resident
        PROC(1, 0);
        ISSUE(1, c + 1);            // prefetch chunk c+1 -> B (max 31)
        WAIT1();                    // chunk c (A) resident
        PROC(0, 0);
    }

    WAIT0();
    PROC(1, 0);                     // chunk 31: consume .. x_511

    // final gates: out = (xs_511 + G(u_511)*u_511) / d0, per row
    float2 o;
    {
        float yv    = fmaf(uv0, LSCALE, MAGIC + LOFF);
        unsigned e  = lut[__float_as_uint(yv) & (LUTN - 1)];
        float rv    = yv - MAGIC;
        float frac  = fmaf(uv0, LSCALE, LOFF - rv);
        unsigned s2 = hfma2u(e >> 16, f2h2(frac, frac), e);
        float s     = H2F_LO(s2);
        o.x = rec * fmaf(s, uv0, xsp0);
    }
    {
        float yv    = fmaf(uv1, LSCALE, MAGIC + LOFF);
        unsigned e  = lut[__float_as_uint(yv) & (LUTN - 1)];
        float rv    = yv - MAGIC;
        float frac  = fmaf(uv1, LSCALE, LOFF - rv);
        unsigned s2 = hfma2u(e >> 16, f2h2(frac, frac), e);
        float s     = H2F_LO(s2);
        o.y = rec * fmaf(s, uv1, xsp1);
    }
    *reinterpret_cast<float2*>(out + r0) = o;
}

extern "C" void kernel_launch(void* const* d_in, const int* in_sizes, int n_in,
                              void* d_out, int out_size)
{
    const float* X    = (const float*)d_in[0];
    const float* W1   = (const float*)d_in[1];
    const float* W2   = (const float*)d_in[2];
    const float* bias = (const float*)d_in[3];
    const float* Wz   = (const float*)d_in[4];
    const float* Ws   = (const float*)d_in[5];
    float* out = (float*)d_out;

    const int batch = out_size;                                 // 65536
    const int grid  = (batch + IL * BLOCK - 1) / (IL * BLOCK);  // 512
    rnn_scan_kernel<<<grid, BLOCK>>>(X, W1, W2, bias, Wz, Ws, out);
}